// round 8
// baseline (speedup 1.0000x reference)
#include <cuda_runtime.h>
#include <cstdint>

// TensorTrain fused kernel (round 1): tf32 mma.sync GEMM + fp32 scan, fully fused.
// BS=16384, N_CH=8, H=256, RANK=16, N_AGGR=4, T=64. Only cols 0..255 of the
// 272-wide ris are ever used (row 16 of the (17,16) reshape is dead).

#define TILE_B 64
#define HS 260   // sh_h / sh_ris row stride in floats (==4 mod 32 -> A-frag conflict-free)
#define US 264   // sh_u row stride in floats (==8 mod 32 -> B-frag conflict-free)

__device__ __forceinline__ float tf32r(float x) {
    unsigned u;
    asm("cvt.rna.tf32.f32 %0, %1;" : "=r"(u) : "f"(x));
    return __uint_as_float(u);
}

__device__ __forceinline__ void mma_tf32(float* d,
    unsigned a0, unsigned a1, unsigned a2, unsigned a3,
    unsigned b0, unsigned b1)
{
    asm volatile(
        "mma.sync.aligned.m16n8k8.row.col.f32.tf32.tf32.f32 "
        "{%0,%1,%2,%3}, {%4,%5,%6,%7}, {%8,%9}, {%0,%1,%2,%3};"
        : "+f"(d[0]), "+f"(d[1]), "+f"(d[2]), "+f"(d[3])
        : "r"(a0), "r"(a1), "r"(a2), "r"(a3), "r"(b0), "r"(b1));
}

extern "C" __global__ void __launch_bounds__(256, 1)
tt_fused_kernel(const float* __restrict__ NH,   // (16384, 8, 256)
                const float* __restrict__ TE,   // (16384, 64)
                const float* __restrict__ Umat, // (8, 4, 256, 272)
                const float* __restrict__ Bv,   // (8, 4, 1, 272)
                const float* __restrict__ UT,   // (4, 64, 16)
                const float* __restrict__ BT,   // (4, 1, 16)
                const float* __restrict__ UO,   // (4, 16, 256)
                const float* __restrict__ BO,   // (4, 1, 256)
                float* __restrict__ out)        // (16384, 1024)
{
    extern __shared__ float smem[];
    float* sh_h     = smem;                 // 64*HS = 16640 floats
    float* sh_u     = sh_h + 64 * HS;       // 32*US =  8448 floats
    float* sh_ris   = sh_u + 32 * US;       // 64*HS = 16640 floats
    float* sh_carry = sh_ris + 64 * HS;     // 64*4*16 = 4096 floats
    float* sh_bias  = sh_carry + 4096;      // 256 floats

    const int tid  = threadIdx.x;
    const int lane = tid & 31;
    const int warp = tid >> 5;
    const int wm   = warp & 3;   // M tile: rows wm*16 .. +15
    const int wn   = warp >> 2;  // N half: cols wn*128 .. +127
    const int gid  = lane >> 2;  // 0..7
    const int tig  = lane & 3;   // 0..3
    const int bbase = blockIdx.x * TILE_B;

    // ---------------- init: carry0 = TE_tile @ U_type + b_type (fp32) -------
    {
        // stage type tile (64x64) into sh_ris scratch, U_type (4096) into sh_u
        float* st  = sh_ris;
        float* sut = sh_u;
        #pragma unroll
        for (int j = 0; j < 4; j++) {
            int id = tid + j * 256;          // 1024 float4
            int s  = id >> 4, c4 = id & 15;
            float4 v = __ldg((const float4*)(TE + (size_t)(bbase + s) * 64 + c4 * 4));
            *(float4*)(st + s * 64 + c4 * 4) = v;
        }
        #pragma unroll
        for (int j = 0; j < 4; j++) {
            int id = tid + j * 256;          // 1024 float4
            float4 v = __ldg(((const float4*)UT) + id);
            *(float4*)(sut + id * 4) = v;
        }
        __syncthreads();
        #pragma unroll
        for (int j = 0; j < 16; j++) {
            int item = tid + j * 256;        // 4096 items
            int s = item >> 6;
            int a = (item >> 4) & 3;
            int q = item & 15;
            float v = __ldg(BT + a * 16 + q);
            const float* srow = st + s * 64;
            const float* ut   = sut + a * 64 * 16 + q;
            #pragma unroll 8
            for (int t = 0; t < 64; t++) v += srow[t] * ut[t * 16];
            sh_carry[(s * 4 + a) * 16 + q] = v;
        }
        __syncthreads();
    }

    // ---------------- main loop: channels x aggregators --------------------
    for (int c = 0; c < 8; c++) {
        // stage h tile (64 x 256) as tf32 into sh_h
        #pragma unroll
        for (int j = 0; j < 16; j++) {
            int id = tid + j * 256;          // 4096 float4
            int s  = id >> 6, c4 = id & 63;
            float4 v = __ldg((const float4*)(NH + ((size_t)(bbase + s) * 8 + c) * 256 + c4 * 4));
            float4 w = make_float4(tf32r(v.x), tf32r(v.y), tf32r(v.z), tf32r(v.w));
            *(float4*)(sh_h + s * HS + c4 * 4) = w;
        }
        // (sync happens inside first k-chunk below before sh_h is read)

        for (int a = 0; a < 4; a++) {
            // stage bias (cols 0..255)
            sh_bias[tid] = __ldg(Bv + (size_t)(c * 4 + a) * 272 + tid);

            float acc[64];
            #pragma unroll
            for (int i = 0; i < 64; i++) acc[i] = 0.f;

            const float* ubase = Umat + (size_t)((c * 4 + a) * 256) * 272;

            for (int kc = 0; kc < 8; kc++) {
                // stage U chunk: rows kc*32..+31, cols 0..255, tf32
                #pragma unroll
                for (int j = 0; j < 8; j++) {
                    int id = tid + j * 256;  // 2048 float4
                    int r  = id >> 6, c4 = id & 63;
                    float4 v = __ldg((const float4*)(ubase + (size_t)(kc * 32 + r) * 272 + c4 * 4));
                    float4 w = make_float4(tf32r(v.x), tf32r(v.y), tf32r(v.z), tf32r(v.w));
                    *(float4*)(sh_u + r * US + c4 * 4) = w;
                }
                __syncthreads();

                #pragma unroll
                for (int ks = 0; ks < 4; ks++) {
                    const int krow = kc * 32 + ks * 8;
                    unsigned a0 = __float_as_uint(sh_h[(wm * 16 + gid) * HS + krow + tig]);
                    unsigned a1 = __float_as_uint(sh_h[(wm * 16 + gid + 8) * HS + krow + tig]);
                    unsigned a2 = __float_as_uint(sh_h[(wm * 16 + gid) * HS + krow + tig + 4]);
                    unsigned a3 = __float_as_uint(sh_h[(wm * 16 + gid + 8) * HS + krow + tig + 4]);
                    #pragma unroll
                    for (int nt = 0; nt < 16; nt++) {
                        int ncol = wn * 128 + nt * 8 + gid;
                        unsigned b0 = __float_as_uint(sh_u[(ks * 8 + tig) * US + ncol]);
                        unsigned b1 = __float_as_uint(sh_u[(ks * 8 + tig + 4) * US + ncol]);
                        mma_tf32(&acc[nt * 4], a0, a1, a2, a3, b0, b1);
                    }
                }
                __syncthreads();
            }

            // store acc + bias -> sh_ris
            #pragma unroll
            for (int nt = 0; nt < 16; nt++) {
                int col = wn * 128 + nt * 8 + tig * 2;
                int row = wm * 16 + gid;
                sh_ris[row * HS + col]           = acc[nt * 4 + 0] + sh_bias[col];
                sh_ris[row * HS + col + 1]       = acc[nt * 4 + 1] + sh_bias[col + 1];
                sh_ris[(row + 8) * HS + col]     = acc[nt * 4 + 2] + sh_bias[col];
                sh_ris[(row + 8) * HS + col + 1] = acc[nt * 4 + 3] + sh_bias[col + 1];
            }
            __syncthreads();

            // scan update: new[q] = ris[240+q] + sum_r carry[r] * ris[r*16+q]
            float nv[4];
            #pragma unroll
            for (int j = 0; j < 4; j++) {
                int item = tid + j * 256;    // 1024 items (64 s x 16 q)
                int s = item >> 4, q = item & 15;
                const float* rr = sh_ris + s * HS;
                const float* cy = sh_carry + (s * 4 + a) * 16;
                float v = rr[240 + q];
                #pragma unroll
                for (int r = 0; r < 16; r++) v += cy[r] * rr[r * 16 + q];
                nv[j] = v;
            }
            __syncthreads();
            #pragma unroll
            for (int j = 0; j < 4; j++) {
                int item = tid + j * 256;
                int s = item >> 4, q = item & 15;
                sh_carry[(s * 4 + a) * 16 + q] = nv[j];
            }
            __syncthreads();
        }
    }

    // ---------------- epilogue: out = carry @ U_output + b_output (fp32) ----
    {
        float* suo = sh_h;  // reuse: 4*16*256 = 16384 floats
        #pragma unroll
        for (int j = 0; j < 16; j++) {
            int id = tid + j * 256;          // 4096 float4
            float4 v = __ldg(((const float4*)UO) + id);
            *(float4*)(suo + id * 4) = v;
        }
        __syncthreads();

        #pragma unroll
        for (int kk = 0; kk < 4; kk++) {     // kk == aggregator a, hh == tid
            float bov = __ldg(BO + kk * 256 + tid);
            const float* uo = suo + kk * 16 * 256 + tid;
            for (int s = 0; s < 64; s++) {
                const float* cy = sh_carry + (s * 4 + kk) * 16;
                float v = bov;
                #pragma unroll
                for (int q = 0; q < 16; q++) v += cy[q] * uo[q * 256];
                out[(size_t)(bbase + s) * 1024 + kk * 256 + tid] = v;
            }
        }
    }
}

extern "C" void kernel_launch(void* const* d_in, const int* in_sizes, int n_in,
                              void* d_out, int out_size)
{
    const float* NH = (const float*)d_in[0];
    const float* TE = (const float*)d_in[1];
    const float* U  = (const float*)d_in[2];
    const float* Bv = (const float*)d_in[3];
    const float* UT = (const float*)d_in[4];
    const float* BT = (const float*)d_in[5];
    const float* UO = (const float*)d_in[6];
    const float* BO = (const float*)d_in[7];
    float* out = (float*)d_out;

    const int smem_bytes = (64 * HS + 32 * US + 64 * HS + 4096 + 256) * 4;
    cudaFuncSetAttribute(tt_fused_kernel,
                         cudaFuncAttributeMaxDynamicSharedMemorySize, smem_bytes);

    tt_fused_kernel<<<16384 / TILE_B, 256, smem_bytes>>>(
        NH, TE, U, Bv, UT, BT, UO, BO, out);
}

// round 10
// speedup vs baseline: 1.5638x; 1.5638x over previous
#include <cuda_runtime.h>
#include <cstdint>

// TensorTrain, round 10: tf32 mma.sync, warp tile 64x64, TILE_B=128 (grid=128,
// one wave), cp.async double-buffered B staging from pre-rounded g_Ut,
// register-resident scan with shared-atomic reduction.
//
// Shapes: NH(16384,8,256) TE(16384,64) U(8,4,256,272) Bv(8,4,1,272)
// UT(4,64,16) BT(4,1,16) UO(4,16,256) BO(4,1,256) -> out(16384,1024).
// Only flat ris cols 0..255 are live (row 16 of the (17,16) reshape is dead);
// b_rank = row 15 (cols 240..255) => coeff(r=15) = carry[15] + 1.

__device__ float g_Ut[32u * 256 * 256];   // [p][k][n] tf32-rounded, 8 MB

__device__ __forceinline__ float tf32r(float x) {
    unsigned u;
    asm("cvt.rna.tf32.f32 %0, %1;" : "=r"(u) : "f"(x));
    return __uint_as_float(u);
}

__device__ __forceinline__ void mma8(float* d,
    unsigned a0, unsigned a1, unsigned a2, unsigned a3,
    unsigned b0, unsigned b1)
{
    asm volatile(
        "mma.sync.aligned.m16n8k8.row.col.f32.tf32.tf32.f32 "
        "{%0,%1,%2,%3}, {%4,%5,%6,%7}, {%8,%9}, {%0,%1,%2,%3};"
        : "+f"(d[0]), "+f"(d[1]), "+f"(d[2]), "+f"(d[3])
        : "r"(a0), "r"(a1), "r"(a2), "r"(a3), "r"(b0), "r"(b1));
}

__device__ __forceinline__ void cpa16(uint32_t dst, const void* src) {
    asm volatile("cp.async.cg.shared.global [%0], [%1], 16;" ::"r"(dst), "l"(src));
}
#define CPCOMMIT() asm volatile("cp.async.commit_group;" ::: "memory")
#define CPWAIT0()  asm volatile("cp.async.wait_group 0;" ::: "memory")

// ---------------- prep: U(8,4,256,272) -> g_Ut[p][k][n<256] (tf32) ---------
extern "C" __global__ void __launch_bounds__(256)
tt_prep(const float* __restrict__ U) {
    const int p  = blockIdx.x;        // 0..31
    const int k0 = blockIdx.y * 32;   // 0..224
    const int n  = threadIdx.x;       // 0..255
    const float* src = U + ((size_t)p * 256 + k0) * 272 + n;
    float* dst = g_Ut + ((size_t)p * 256 + k0) * 256 + n;
    #pragma unroll
    for (int kk = 0; kk < 32; kk++)
        dst[kk * 256] = tf32r(__ldg(src + kk * 272));
}

// ---------------- main ------------------------------------------------------
// SMEM (floats): sA [0,33280)  128 rows x stride 260
//                sU0 [33280,41472)  sU1 [41472,49664)   32-row B chunks,
//                    blocked layout: elem(row,n) at (n>>3)*256 + row*8 + (n&7)
//                sC  [49664,57856)  carry [s][a][q] = s*64+a*16+q
//                sNC = sU0 head [33280,35328)  newcarry [s][q] (overlay)
#define SA   0
#define SU0  33280
#define SU1  41472
#define SCAR 49664
#define SNC  33280
#define SMEM_BYTES (57856 * 4)

extern "C" __global__ void __launch_bounds__(256, 1)
tt_main(const float* __restrict__ NH, const float* __restrict__ TE,
        const float* __restrict__ Bv, const float* __restrict__ UT,
        const float* __restrict__ BT, const float* __restrict__ UO,
        const float* __restrict__ BO, float* __restrict__ out)
{
    extern __shared__ float sm[];
    float* sA  = sm + SA;
    float* sC  = sm + SCAR;
    float* sNC = sm + SNC;

    uint32_t smb;
    asm("{ .reg .u64 t; cvta.to.shared.u64 t, %1; cvt.u32.u64 %0, t; }"
        : "=r"(smb) : "l"(sm));

    const int tid  = threadIdx.x;
    const int lane = tid & 31;
    const int warp = tid >> 5;
    const int wm   = warp & 1;    // M: rows wm*64 .. +63
    const int wn   = warp >> 1;   // N: cols wn*64 .. +63
    const int gid  = lane >> 2;
    const int tig  = lane & 3;
    const int bbase = blockIdx.x * 128;

    // ---- init: carry0[s][a][:] = BT[a] + TE_tile[s] @ UT[a] ----------------
    {
        #pragma unroll
        for (int j = 0; j < 8; j++) {             // TE tile 128x64 -> sA
            int id = tid + j * 256;               // 2048 float4
            int s = id >> 4, c4 = id & 15;
            ((float4*)(sA + s * 64))[c4] =
                __ldg((const float4*)(TE + (size_t)(bbase + s) * 64) + c4);
        }
        #pragma unroll
        for (int j = 0; j < 4; j++) {             // UT 4096 floats -> sU0
            int id = tid + j * 256;
            ((float4*)(sm + SU0))[id] = __ldg(((const float4*)UT) + id);
        }
        __syncthreads();
        #pragma unroll
        for (int pp = 0; pp < 2; pp++) {
            int item = tid + pp * 256;            // 512 (s,a) pairs
            int s = item >> 2, a = item & 3;
            float cr[16];
            #pragma unroll
            for (int q = 0; q < 16; q++) cr[q] = __ldg(BT + a * 16 + q);
            const float* te = sA + s * 64;
            const float* ut = sm + SU0 + a * 64 * 16;
            for (int t = 0; t < 64; t++) {
                float v = te[t];
                #pragma unroll
                for (int q = 0; q < 16; q++)
                    cr[q] = fmaf(v, ut[t * 16 + q], cr[q]);
            }
            #pragma unroll
            for (int q = 0; q < 16; q++) sC[s * 64 + a * 16 + q] = cr[q];
        }
        __syncthreads();
    }

    const int arow = tid >> 1;            // A staging: row, 2 threads/row
    const int akb  = (tid & 1) * 128;

    // ---- main loop ---------------------------------------------------------
    for (int c = 0; c < 8; c++) {
        for (int a = 0; a < 4; a++) {
            const int p = c * 4 + a;

            // issue chunk 0 -> buf0
            {
                const float* src = g_Ut + ((size_t)p * 256) * 256;
                #pragma unroll
                for (int j = 0; j < 8; j++) {
                    int id = tid + j * 256;           // 2048 float4
                    int row = id >> 6, nq = id & 63;
                    uint32_t d = smb + (uint32_t)(SU0 + ((nq >> 1) * 32 + row) * 8
                                                  + (nq & 1) * 4) * 4;
                    cpa16(d, src + row * 256 + nq * 4);
                }
                CPCOMMIT();
            }

            if (a == 0) {   // stage A(c): 128x256 fp32->tf32, stride 260
                const float4* srcA = (const float4*)(NH +
                    ((size_t)(bbase + arow) * 8 + c) * 256 + akb);
                float* dA = sA + arow * 260 + akb;
                #pragma unroll 8
                for (int j = 0; j < 32; j++) {
                    float4 v = __ldg(srcA + j);
                    *(float4*)(dA + j * 4) = make_float4(
                        tf32r(v.x), tf32r(v.y), tf32r(v.z), tf32r(v.w));
                }
            }

            float acc[128];
            #pragma unroll
            for (int i = 0; i < 128; i++) acc[i] = 0.f;

            #pragma unroll 1
            for (int kc = 0; kc < 8; kc++) {
                CPWAIT0();
                __syncthreads();
                if (kc < 7) {   // prefetch chunk kc+1 into buf[(kc+1)&1]
                    const int bo = (kc & 1) ? SU0 : SU1;
                    const float* src = g_Ut + ((size_t)p * 256 + (kc + 1) * 32) * 256;
                    #pragma unroll
                    for (int j = 0; j < 8; j++) {
                        int id = tid + j * 256;
                        int row = id >> 6, nq = id & 63;
                        uint32_t d = smb + (uint32_t)(bo + ((nq >> 1) * 32 + row) * 8
                                                      + (nq & 1) * 4) * 4;
                        cpa16(d, src + row * 256 + nq * 4);
                    }
                    CPCOMMIT();
                } else {        // zero newcarry (buf0 head; buf0 idle: chunk7 is in buf1)
                    ((float4*)sNC)[tid]       = make_float4(0.f, 0.f, 0.f, 0.f);
                    ((float4*)sNC)[tid + 256] = make_float4(0.f, 0.f, 0.f, 0.f);
                }

                // compute chunk kc from buf[kc&1]
                const float* bufp = sm + ((kc & 1) ? SU1 : SU0);
                #pragma unroll
                for (int ks = 0; ks < 4; ks++) {
                    const int kg = kc * 32 + ks * 8;
                    unsigned Af[4][4];
                    #pragma unroll
                    for (int mt = 0; mt < 4; mt++) {
                        const float* ap = sA + (wm * 64 + mt * 16 + gid) * 260 + kg + tig;
                        Af[mt][0] = __float_as_uint(ap[0]);
                        Af[mt][1] = __float_as_uint(ap[8 * 260]);
                        Af[mt][2] = __float_as_uint(ap[4]);
                        Af[mt][3] = __float_as_uint(ap[8 * 260 + 4]);
                    }
                    #pragma unroll
                    for (int nt = 0; nt < 8; nt++) {
                        const float* bp = bufp + (wn * 8 + nt) * 256 + (ks * 8 + tig) * 8 + gid;
                        unsigned b0 = __float_as_uint(bp[0]);
                        unsigned b1 = __float_as_uint(bp[32]);
                        #pragma unroll
                        for (int mt = 0; mt < 4; mt++)
                            mma8(acc + (mt * 8 + nt) * 4,
                                 Af[mt][0], Af[mt][1], Af[mt][2], Af[mt][3], b0, b1);
                    }
                }
            }
            __syncthreads();   // all GEMM + nc-zero done

            // ---- scan: fold acc into newcarry via shared atomics -----------
            float bias[16];
            #pragma unroll
            for (int nt = 0; nt < 8; nt++) {
                const int colb = wn * 64 + nt * 8 + tig * 2;
                bias[nt * 2]     = __ldg(Bv + (size_t)p * 272 + colb);
                bias[nt * 2 + 1] = __ldg(Bv + (size_t)p * 272 + colb + 1);
            }
            #pragma unroll
            for (int mt = 0; mt < 4; mt++) {
                #pragma unroll
                for (int o = 0; o < 2; o++) {
                    const int s = wm * 64 + mt * 16 + o * 8 + gid;
                    float cf[4];
                    #pragma unroll
                    for (int m = 0; m < 4; m++)
                        cf[m] = sC[s * 64 + a * 16 + wn * 4 + m];
                    if (wn == 3) cf[3] += 1.0f;   // standalone b_rank (r=15) term
                    #pragma unroll
                    for (int pq = 0; pq < 2; pq++) {
                        #pragma unroll
                        for (int e = 0; e < 2; e++) {
                            float P = 0.f;
                            #pragma unroll
                            for (int m = 0; m < 4; m++) {
                                const int nt = 2 * m + pq;
                                P = fmaf(cf[m],
                                         acc[(mt * 8 + nt) * 4 + o * 2 + e] + bias[nt * 2 + e],
                                         P);
                            }
                            atomicAdd(&sNC[s * 16 + pq * 8 + tig * 2 + e], P);
                        }
                    }
                }
            }
            __syncthreads();
            // copy newcarry -> carry[a]
            #pragma unroll
            for (int j = 0; j < 2; j++) {
                const int id = tid + j * 256;      // 512 float4
                const int s = id >> 2, f = id & 3;
                ((float4*)(sC + s * 64 + a * 16))[f] = ((const float4*)sNC)[id];
            }
            __syncthreads();
        }
    }

    // ---- epilogue: out = carry @ U_output + b_output -----------------------
    #pragma unroll
    for (int j = 0; j < 16; j++) {       // UO 16384 floats -> sA
        const int id = tid + j * 256;
        ((float4*)sA)[id] = __ldg(((const float4*)UO) + id);
    }
    __syncthreads();
    const int h = tid;
    #pragma unroll
    for (int a = 0; a < 4; a++) {
        float uo[16];
        #pragma unroll
        for (int q = 0; q < 16; q++) uo[q] = sA[(a * 16 + q) * 256 + h];
        const float bo = __ldg(BO + a * 256 + h);
        #pragma unroll 2
        for (int s = 0; s < 128; s++) {
            const float4* cp4 = (const float4*)(sC + s * 64 + a * 16);
            float4 c0 = cp4[0], c1 = cp4[1], c2 = cp4[2], c3 = cp4[3];
            float v = bo;
            v = fmaf(c0.x, uo[0], v);  v = fmaf(c0.y, uo[1], v);
            v = fmaf(c0.z, uo[2], v);  v = fmaf(c0.w, uo[3], v);
            v = fmaf(c1.x, uo[4], v);  v = fmaf(c1.y, uo[5], v);
            v = fmaf(c1.z, uo[6], v);  v = fmaf(c1.w, uo[7], v);
            v = fmaf(c2.x, uo[8], v);  v = fmaf(c2.y, uo[9], v);
            v = fmaf(c2.z, uo[10], v); v = fmaf(c2.w, uo[11], v);
            v = fmaf(c3.x, uo[12], v); v = fmaf(c3.y, uo[13], v);
            v = fmaf(c3.z, uo[14], v); v = fmaf(c3.w, uo[15], v);
            out[(size_t)(bbase + s) * 1024 + a * 256 + h] = v;
        }
    }
}

// ---------------- launch ----------------------------------------------------
extern "C" void kernel_launch(void* const* d_in, const int* in_sizes, int n_in,
                              void* d_out, int out_size)
{
    const float* NH = (const float*)d_in[0];
    const float* TE = (const float*)d_in[1];
    const float* U  = (const float*)d_in[2];
    const float* Bv = (const float*)d_in[3];
    const float* UT = (const float*)d_in[4];
    const float* BT = (const float*)d_in[5];
    const float* UO = (const float*)d_in[6];
    const float* BO = (const float*)d_in[7];
    float* out = (float*)d_out;

    tt_prep<<<dim3(32, 8), 256>>>(U);

    cudaFuncSetAttribute(tt_main, cudaFuncAttributeMaxDynamicSharedMemorySize,
                         SMEM_BYTES);
    tt_main<<<128, 256, SMEM_BYTES>>>(NH, TE, Bv, UT, BT, UO, BO, out);
}

// round 14
// speedup vs baseline: 2.6080x; 1.6677x over previous
#include <cuda_runtime.h>
#include <cuda_fp16.h>
#include <cstdint>

// TensorTrain, round 11: fp16 mma.sync m16n8k16 (same 11-bit mantissa as tf32),
// warp tile 64x64, TILE_B=128 (grid=128, one wave), cp.async double-buffered B
// from pre-packed fp16 g_Uh, register-resident scan + shared-atomic reduction.
//
// Shapes: NH(16384,8,256) TE(16384,64) U(8,4,256,272) Bv(8,4,1,272)
// UT(4,64,16) BT(4,1,16) UO(4,16,256) BO(4,1,256) -> out(16384,1024).
// Only flat ris cols 0..255 live; b_rank = row 15 => coeff(r=15) = carry[15]+1.

__device__ unsigned g_Uh[32u * 8 * 4096];   // [p][chunk] blocked half2 image, 4 MB

__device__ __forceinline__ void mma16(float* d,
    unsigned a0, unsigned a1, unsigned a2, unsigned a3,
    unsigned b0, unsigned b1)
{
    asm volatile(
        "mma.sync.aligned.m16n8k16.row.col.f32.f16.f16.f32 "
        "{%0,%1,%2,%3}, {%4,%5,%6,%7}, {%8,%9}, {%0,%1,%2,%3};"
        : "+f"(d[0]), "+f"(d[1]), "+f"(d[2]), "+f"(d[3])
        : "r"(a0), "r"(a1), "r"(a2), "r"(a3), "r"(b0), "r"(b1));
}

__device__ __forceinline__ void cpa16(uint32_t dst, const void* src) {
    asm volatile("cp.async.cg.shared.global [%0], [%1], 16;" ::"r"(dst), "l"(src));
}
#define CPCOMMIT() asm volatile("cp.async.commit_group;" ::: "memory")
#define CPWAIT0()  asm volatile("cp.async.wait_group 0;" ::: "memory")

__device__ __forceinline__ unsigned h2u(__half2 h) {
    return *reinterpret_cast<unsigned*>(&h);
}

// ---- prep: U(8,4,256,272) -> g_Uh[p][chunk][(n>>3)*128 + kp*8 + (n&7)] ----
// half2 pairs consecutive k: kp = (k_local)/2, .x = even k (lower address).
extern "C" __global__ void __launch_bounds__(256)
tt_prep(const float* __restrict__ U) {
    const int p  = blockIdx.x;        // 0..31
    const int ch = blockIdx.y;        // 0..7
    const int n  = threadIdx.x;       // 0..255
    unsigned* dst = g_Uh + ((size_t)(p * 8 + ch)) * 4096 + (n >> 3) * 128 + (n & 7);
    const float* src = U + ((size_t)(p * 256 + ch * 32)) * 272 + n;
    #pragma unroll
    for (int kp = 0; kp < 16; kp++) {
        float f0 = __ldg(src + (2 * kp) * 272);
        float f1 = __ldg(src + (2 * kp + 1) * 272);
        dst[kp * 8] = h2u(__floats2half2_rn(f0, f1));
    }
}

// ---- main ------------------------------------------------------------------
// SMEM (uint units): A  [0, 16896)        128 rows x 132 half2  (67.5 KB)
//                    B0 [16896, 20992)    16 KB chunk
//                    B1 [20992, 25088)    16 KB chunk
//                    C  [25088, 33280)    carry [s][a][q] f32    (32 KB)
//                    NC overlays B0 head  [16896, 18944)  [s][q] f32
#define UA   0
#define UB0  16896
#define UB1  20992
#define UCAR 25088
#define UNC  16896
#define SMEM_BYTES (33280 * 4)

extern "C" __global__ void __launch_bounds__(256, 1)
tt_main(const float* __restrict__ NH, const float* __restrict__ TE,
        const float* __restrict__ Bv, const float* __restrict__ UT,
        const float* __restrict__ BT, const float* __restrict__ UO,
        const float* __restrict__ BO, float* __restrict__ out)
{
    extern __shared__ float sm[];
    unsigned* sA2 = (unsigned*)sm;            // half2 units
    float*    sC  = sm + UCAR;
    float*    sNC = sm + UNC;

    uint32_t smb;
    asm("{ .reg .u64 t; cvta.to.shared.u64 t, %1; cvt.u32.u64 %0, t; }"
        : "=r"(smb) : "l"(sm));

    const int tid  = threadIdx.x;
    const int lane = tid & 31;
    const int warp = tid >> 5;
    const int wm   = warp & 1;    // M: rows wm*64 .. +63
    const int wn   = warp >> 1;   // N: cols wn*64 .. +63
    const int gid  = lane >> 2;
    const int tig  = lane & 3;
    const int bbase = blockIdx.x * 128;

    // ---- init: carry0[s][a][:] = BT[a] + TE_tile[s] @ UT[a] (fp32) ---------
    {
        float* sTE = sm;              // 128x64 floats in A region
        float* sUT = sm + UB0;        // 4096 floats in B0
        #pragma unroll
        for (int j = 0; j < 8; j++) {
            int id = tid + j * 256;   // 2048 float4
            int s = id >> 4, c4 = id & 15;
            ((float4*)(sTE + s * 64))[c4] =
                __ldg((const float4*)(TE + (size_t)(bbase + s) * 64) + c4);
        }
        #pragma unroll
        for (int j = 0; j < 4; j++) {
            int id = tid + j * 256;
            ((float4*)sUT)[id] = __ldg(((const float4*)UT) + id);
        }
        __syncthreads();
        #pragma unroll
        for (int pp = 0; pp < 2; pp++) {
            int item = tid + pp * 256;   // 512 (s,a) pairs
            int s = item >> 2, a = item & 3;
            float cr[16];
            #pragma unroll
            for (int q = 0; q < 16; q++) cr[q] = __ldg(BT + a * 16 + q);
            const float* te = sTE + s * 64;
            const float* ut = sUT + a * 64 * 16;
            for (int t = 0; t < 64; t++) {
                float v = te[t];
                #pragma unroll
                for (int q = 0; q < 16; q++)
                    cr[q] = fmaf(v, ut[t * 16 + q], cr[q]);
            }
            #pragma unroll
            for (int q = 0; q < 16; q++) sC[s * 64 + a * 16 + q] = cr[q];
        }
        __syncthreads();
    }

    const int arow = tid >> 1;            // A staging: 2 threads/row
    const int akb  = (tid & 1) * 128;     // float col base
    const int akpb = (tid & 1) * 64;      // half2 col base

    // ---- main loop ---------------------------------------------------------
    for (int c = 0; c < 8; c++) {
        for (int a = 0; a < 4; a++) {
            const int p = c * 4 + a;

            // issue B chunk 0 -> buf0 (16 KB contiguous)
            {
                const unsigned* src = g_Uh + (size_t)(p * 8) * 4096;
                #pragma unroll
                for (int j = 0; j < 4; j++) {
                    int id = tid + j * 256;          // 1024 x 16B
                    cpa16(smb + (uint32_t)(UB0 + id * 4) * 4, src + id * 4);
                }
                CPCOMMIT();
            }

            if (a == 0) {   // stage A(c): 128x256 fp32->half2, stride 132
                const float4* srcA = (const float4*)(NH +
                    ((size_t)(bbase + arow) * 8 + c) * 256 + akb);
                unsigned* dA = sA2 + arow * 132 + akpb;
                #pragma unroll 8
                for (int j = 0; j < 32; j++) {
                    float4 v = __ldg(srcA + j);
                    uint2 w;
                    w.x = h2u(__floats2half2_rn(v.x, v.y));
                    w.y = h2u(__floats2half2_rn(v.z, v.w));
                    *(uint2*)(dA + j * 2) = w;
                }
            }

            float acc[128];
            #pragma unroll
            for (int i = 0; i < 128; i++) acc[i] = 0.f;

            #pragma unroll 1
            for (int kc = 0; kc < 8; kc++) {
                CPWAIT0();
                __syncthreads();
                if (kc < 7) {   // prefetch chunk kc+1 -> buf[(kc+1)&1]
                    const int bo = (kc & 1) ? UB0 : UB1;
                    const unsigned* src = g_Uh + (size_t)(p * 8 + kc + 1) * 4096;
                    #pragma unroll
                    for (int j = 0; j < 4; j++) {
                        int id = tid + j * 256;
                        cpa16(smb + (uint32_t)(bo + id * 4) * 4, src + id * 4);
                    }
                    CPCOMMIT();
                } else {        // zero newcarry (buf0 head; chunk 7 is in buf1)
                    ((float4*)sNC)[tid]       = make_float4(0.f, 0.f, 0.f, 0.f);
                    ((float4*)sNC)[tid + 256] = make_float4(0.f, 0.f, 0.f, 0.f);
                }

                // compute chunk kc from buf[kc&1]: two k16 steps
                const unsigned* bufp = (const unsigned*)sm + ((kc & 1) ? UB1 : UB0);
                #pragma unroll
                for (int ksl = 0; ksl < 2; ksl++) {
                    const int kpb = kc * 16 + ksl * 8;   // global half2 col base
                    unsigned Af[4][4];
                    #pragma unroll
                    for (int mt = 0; mt < 4; mt++) {
                        const unsigned* ap = sA2 + (wm * 64 + mt * 16 + gid) * 132 + kpb + tig;
                        Af[mt][0] = ap[0];           // (gid,   k 2t..2t+1)
                        Af[mt][1] = ap[8 * 132];     // (gid+8, k 2t..2t+1)
                        Af[mt][2] = ap[4];           // (gid,   k 2t+8..)
                        Af[mt][3] = ap[8 * 132 + 4]; // (gid+8, k 2t+8..)
                    }
                    #pragma unroll
                    for (int nt = 0; nt < 8; nt++) {
                        const unsigned* bp = bufp + (wn * 8 + nt) * 128
                                           + (ksl * 8 + tig) * 8 + gid;
                        unsigned b0 = bp[0];     // k 2t..2t+1
                        unsigned b1 = bp[32];    // k 2t+8..2t+9
                        #pragma unroll
                        for (int mt = 0; mt < 4; mt++)
                            mma16(acc + (mt * 8 + nt) * 4,
                                  Af[mt][0], Af[mt][1], Af[mt][2], Af[mt][3], b0, b1);
                    }
                }
            }
            __syncthreads();   // all GEMM + nc-zero done

            // ---- scan: fold acc into newcarry via shared atomics -----------
            float bias[16];
            #pragma unroll
            for (int nt = 0; nt < 8; nt++) {
                const int colb = wn * 64 + nt * 8 + tig * 2;
                bias[nt * 2]     = __ldg(Bv + (size_t)p * 272 + colb);
                bias[nt * 2 + 1] = __ldg(Bv + (size_t)p * 272 + colb + 1);
            }
            #pragma unroll
            for (int mt = 0; mt < 4; mt++) {
                #pragma unroll
                for (int o = 0; o < 2; o++) {
                    const int s = wm * 64 + mt * 16 + o * 8 + gid;
                    float cf[4];
                    #pragma unroll
                    for (int m = 0; m < 4; m++)
                        cf[m] = sC[s * 64 + a * 16 + wn * 4 + m];
                    if (wn == 3) cf[3] += 1.0f;   // standalone b_rank (r=15)
                    #pragma unroll
                    for (int pq = 0; pq < 2; pq++) {
                        #pragma unroll
                        for (int e = 0; e < 2; e++) {
                            float P = 0.f;
                            #pragma unroll
                            for (int m = 0; m < 4; m++) {
                                const int nt = 2 * m + pq;
                                P = fmaf(cf[m],
                                         acc[(mt * 8 + nt) * 4 + o * 2 + e] + bias[nt * 2 + e],
                                         P);
                            }
                            atomicAdd(&sNC[s * 16 + pq * 8 + tig * 2 + e], P);
                        }
                    }
                }
            }
            __syncthreads();
            // copy newcarry -> carry[a]
            #pragma unroll
            for (int j = 0; j < 2; j++) {
                const int id = tid + j * 256;      // 512 float4
                const int s = id >> 2, f = id & 3;
                ((float4*)(sC + s * 64 + a * 16))[f] = ((const float4*)sNC)[id];
            }
            __syncthreads();
        }
    }

    // ---- epilogue: out = carry @ U_output + b_output -----------------------
    float* sUO = sm;   // 16384 floats in A region
    #pragma unroll
    for (int j = 0; j < 16; j++) {
        const int id = tid + j * 256;
        ((float4*)sUO)[id] = __ldg(((const float4*)UO) + id);
    }
    __syncthreads();
    const int h = tid;
    #pragma unroll
    for (int a = 0; a < 4; a++) {
        float uo[16];
        #pragma unroll
        for (int q = 0; q < 16; q++) uo[q] = sUO[(a * 16 + q) * 256 + h];
        const float bo = __ldg(BO + a * 256 + h);
        #pragma unroll 2
        for (int s = 0; s < 128; s++) {
            const float4* cp4 = (const float4*)(sC + s * 64 + a * 16);
            float4 c0 = cp4[0], c1 = cp4[1], c2 = cp4[2], c3 = cp4[3];
            float v = bo;
            v = fmaf(c0.x, uo[0], v);  v = fmaf(c0.y, uo[1], v);
            v = fmaf(c0.z, uo[2], v);  v = fmaf(c0.w, uo[3], v);
            v = fmaf(c1.x, uo[4], v);  v = fmaf(c1.y, uo[5], v);
            v = fmaf(c1.z, uo[6], v);  v = fmaf(c1.w, uo[7], v);
            v = fmaf(c2.x, uo[8], v);  v = fmaf(c2.y, uo[9], v);
            v = fmaf(c2.z, uo[10], v); v = fmaf(c2.w, uo[11], v);
            v = fmaf(c3.x, uo[12], v); v = fmaf(c3.y, uo[13], v);
            v = fmaf(c3.z, uo[14], v); v = fmaf(c3.w, uo[15], v);
            out[(size_t)(bbase + s) * 1024 + a * 256 + h] = v;
        }
    }
}

// ---- launch ----------------------------------------------------------------
extern "C" void kernel_launch(void* const* d_in, const int* in_sizes, int n_in,
                              void* d_out, int out_size)
{
    const float* NH = (const float*)d_in[0];
    const float* TE = (const float*)d_in[1];
    const float* U  = (const float*)d_in[2];
    const float* Bv = (const float*)d_in[3];
    const float* UT = (const float*)d_in[4];
    const float* BT = (const float*)d_in[5];
    const float* UO = (const float*)d_in[6];
    const float* BO = (const float*)d_in[7];
    float* out = (float*)d_out;

    tt_prep<<<dim3(32, 8), 256>>>(U);

    cudaFuncSetAttribute(tt_main, cudaFuncAttributeMaxDynamicSharedMemorySize,
                         SMEM_BYTES);
    tt_main<<<128, 256, SMEM_BYTES>>>(NH, TE, Bv, UT, BT, UO, BO, out);
}

// round 17
// speedup vs baseline: 2.9587x; 1.1345x over previous
#include <cuda_runtime.h>
#include <cuda_fp16.h>
#include <cstdint>

// TensorTrain, round 15: fp16 mma.sync m16n8k16, warp tile 64x64, TILE_B=128
// (grid=128, one wave), cp.async double-buffered B from pre-packed fp16 g_Uh,
// register-resident scan with SLAB reduction (no shared atomics).
//
// Shapes: NH(16384,8,256) TE(16384,64) U(8,4,256,272) Bv(8,4,1,272)
// UT(4,64,16) BT(4,1,16) UO(4,16,256) BO(4,1,256) -> out(16384,1024).
// Only flat ris cols 0..255 live; b_rank = row 15 => coeff(r=15) = carry[15]+1.

__device__ unsigned g_Uh[32u * 8 * 4096];   // [p][chunk] blocked half2 image, 4 MB

__device__ __forceinline__ void mma16(float* d,
    unsigned a0, unsigned a1, unsigned a2, unsigned a3,
    unsigned b0, unsigned b1)
{
    asm volatile(
        "mma.sync.aligned.m16n8k16.row.col.f32.f16.f16.f32 "
        "{%0,%1,%2,%3}, {%4,%5,%6,%7}, {%8,%9}, {%0,%1,%2,%3};"
        : "+f"(d[0]), "+f"(d[1]), "+f"(d[2]), "+f"(d[3])
        : "r"(a0), "r"(a1), "r"(a2), "r"(a3), "r"(b0), "r"(b1));
}

__device__ __forceinline__ void cpa16(uint32_t dst, const void* src) {
    asm volatile("cp.async.cg.shared.global [%0], [%1], 16;" ::"r"(dst), "l"(src));
}
#define CPCOMMIT() asm volatile("cp.async.commit_group;" ::: "memory")
#define CPWAIT0()  asm volatile("cp.async.wait_group 0;" ::: "memory")

__device__ __forceinline__ unsigned h2u(__half2 h) {
    return *reinterpret_cast<unsigned*>(&h);
}

// ---- prep: U(8,4,256,272) -> g_Uh[p][chunk][(n>>3)*128 + kp*8 + (n&7)] ----
extern "C" __global__ void __launch_bounds__(256)
tt_prep(const float* __restrict__ U) {
    const int p  = blockIdx.x;        // 0..31
    const int ch = blockIdx.y;        // 0..7
    const int n  = threadIdx.x;       // 0..255
    unsigned* dst = g_Uh + ((size_t)(p * 8 + ch)) * 4096 + (n >> 3) * 128 + (n & 7);
    const float* src = U + ((size_t)(p * 256 + ch * 32)) * 272 + n;
    #pragma unroll
    for (int kp = 0; kp < 16; kp++) {
        float f0 = __ldg(src + (2 * kp) * 272);
        float f1 = __ldg(src + (2 * kp + 1) * 272);
        dst[kp * 8] = h2u(__floats2half2_rn(f0, f1));
    }
}

// ---- main ------------------------------------------------------------------
// SMEM (32-bit units): A   [0, 16896)       128 rows x 132 half2  (67.5 KB)
//                      B0  [16896, 20992)   16 KB chunk
//                      B1  [20992, 25088)   16 KB chunk
//                      C   [25088, 33280)   carry [s][a][q] f32   (32 KB)
//                      SLB [33280, 41728)   4 slabs x (16 q x 132) f32 (33 KB)
#define UA   0
#define UB0  16896
#define UB1  20992
#define UCAR 25088
#define USLB 33280
#define SMEM_BYTES (41728 * 4)

extern "C" __global__ void __launch_bounds__(256, 1)
tt_main(const float* __restrict__ NH, const float* __restrict__ TE,
        const float* __restrict__ Bv, const float* __restrict__ UT,
        const float* __restrict__ BT, const float* __restrict__ UO,
        const float* __restrict__ BO, float* __restrict__ out)
{
    extern __shared__ float sm[];
    unsigned* sA2   = (unsigned*)sm;          // half2 units
    float*    sC    = sm + UCAR;
    float*    sSlab = sm + USLB;

    uint32_t smb;
    asm("{ .reg .u64 t; cvta.to.shared.u64 t, %1; cvt.u32.u64 %0, t; }"
        : "=r"(smb) : "l"(sm));

    const int tid  = threadIdx.x;
    const int lane = tid & 31;
    const int warp = tid >> 5;
    const int wm   = warp & 1;    // M: rows wm*64 .. +63
    const int wn   = warp >> 1;   // N: cols wn*64 .. +63
    const int gid  = lane >> 2;
    const int tig  = lane & 3;
    const int bbase = blockIdx.x * 128;

    // ---- init: carry0[s][a][:] = BT[a] + TE_tile[s] @ UT[a] (fp32) ---------
    {
        float* sTE = sm;              // 128x64 floats in A region
        float* sUT = sm + UB0;        // 4096 floats in B0
        #pragma unroll
        for (int j = 0; j < 8; j++) {
            int id = tid + j * 256;   // 2048 float4
            int s = id >> 4, c4 = id & 15;
            ((float4*)(sTE + s * 64))[c4] =
                __ldg((const float4*)(TE + (size_t)(bbase + s) * 64) + c4);
        }
        #pragma unroll
        for (int j = 0; j < 4; j++) {
            int id = tid + j * 256;
            ((float4*)sUT)[id] = __ldg(((const float4*)UT) + id);
        }
        __syncthreads();
        #pragma unroll
        for (int pp = 0; pp < 2; pp++) {
            int item = tid + pp * 256;   // 512 (s,a) pairs
            int s = item >> 2, a = item & 3;
            float cr[16];
            #pragma unroll
            for (int q = 0; q < 16; q++) cr[q] = __ldg(BT + a * 16 + q);
            const float* te = sTE + s * 64;
            const float* ut = sUT + a * 64 * 16;
            for (int t = 0; t < 64; t++) {
                float v = te[t];
                #pragma unroll
                for (int q = 0; q < 16; q++)
                    cr[q] = fmaf(v, ut[t * 16 + q], cr[q]);
            }
            #pragma unroll
            for (int q = 0; q < 16; q++) sC[s * 64 + a * 16 + q] = cr[q];
        }
        __syncthreads();
    }

    const int arow = tid >> 1;            // A staging: 2 threads/row
    const int akb  = (tid & 1) * 128;     // float col base
    const int akpb = (tid & 1) * 64;      // half2 col base

    // ---- main loop ---------------------------------------------------------
    for (int c = 0; c < 8; c++) {
        for (int a = 0; a < 4; a++) {
            const int p = c * 4 + a;

            // issue B chunk 0 -> buf0 (16 KB contiguous)
            {
                const unsigned* src = g_Uh + (size_t)(p * 8) * 4096;
                #pragma unroll
                for (int j = 0; j < 4; j++) {
                    int id = tid + j * 256;          // 1024 x 16B
                    cpa16(smb + (uint32_t)(UB0 + id * 4) * 4, src + id * 4);
                }
                CPCOMMIT();
            }

            if (a == 0) {   // stage A(c): 128x256 fp32->half2, stride 132
                const float4* srcA = (const float4*)(NH +
                    ((size_t)(bbase + arow) * 8 + c) * 256 + akb);
                unsigned* dA = sA2 + arow * 132 + akpb;
                #pragma unroll 8
                for (int j = 0; j < 32; j++) {
                    float4 v = __ldg(srcA + j);
                    uint2 w;
                    w.x = h2u(__floats2half2_rn(v.x, v.y));
                    w.y = h2u(__floats2half2_rn(v.z, v.w));
                    *(uint2*)(dA + j * 2) = w;
                }
            }

            float acc[128];
            #pragma unroll
            for (int i = 0; i < 128; i++) acc[i] = 0.f;

            #pragma unroll 1
            for (int kc = 0; kc < 8; kc++) {
                CPWAIT0();
                __syncthreads();
                if (kc < 7) {   // prefetch chunk kc+1 -> buf[(kc+1)&1]
                    const int bo = (kc & 1) ? UB0 : UB1;
                    const unsigned* src = g_Uh + (size_t)(p * 8 + kc + 1) * 4096;
                    #pragma unroll
                    for (int j = 0; j < 4; j++) {
                        int id = tid + j * 256;
                        cpa16(smb + (uint32_t)(bo + id * 4) * 4, src + id * 4);
                    }
                    CPCOMMIT();
                }

                // compute chunk kc from buf[kc&1]: two k16 steps
                const unsigned* bufp = (const unsigned*)sm + ((kc & 1) ? UB1 : UB0);
                #pragma unroll
                for (int ksl = 0; ksl < 2; ksl++) {
                    const int kpb = kc * 16 + ksl * 8;   // global half2 col base
                    unsigned Af[4][4];
                    #pragma unroll
                    for (int mt = 0; mt < 4; mt++) {
                        const unsigned* ap = sA2 + (wm * 64 + mt * 16 + gid) * 132 + kpb + tig;
                        Af[mt][0] = ap[0];
                        Af[mt][1] = ap[8 * 132];
                        Af[mt][2] = ap[4];
                        Af[mt][3] = ap[8 * 132 + 4];
                    }
                    #pragma unroll
                    for (int nt = 0; nt < 8; nt++) {
                        const unsigned* bp = bufp + (wn * 8 + nt) * 128
                                           + (ksl * 8 + tig) * 8 + gid;
                        unsigned b0 = bp[0];
                        unsigned b1 = bp[32];
                        #pragma unroll
                        for (int mt = 0; mt < 4; mt++)
                            mma16(acc + (mt * 8 + nt) * 4,
                                  Af[mt][0], Af[mt][1], Af[mt][2], Af[mt][3], b0, b1);
                    }
                }
            }
            // NOTE: no sync needed here — each warp writes only its own slab.

            // ---- scan partials -> private slab (conflict-free STS) ---------
            float bias[16];
            #pragma unroll
            for (int nt = 0; nt < 8; nt++) {
                const int colb = wn * 64 + nt * 8 + tig * 2;
                bias[nt * 2]     = __ldg(Bv + (size_t)p * 272 + colb);
                bias[nt * 2 + 1] = __ldg(Bv + (size_t)p * 272 + colb + 1);
            }
            float* mySlab = sSlab + wn * 2112;
            #pragma unroll
            for (int mt = 0; mt < 4; mt++) {
                #pragma unroll
                for (int o = 0; o < 2; o++) {
                    const int s = wm * 64 + mt * 16 + o * 8 + gid;
                    float cf[4];
                    #pragma unroll
                    for (int m = 0; m < 4; m++)
                        cf[m] = sC[s * 64 + a * 16 + wn * 4 + m];
                    if (wn == 3) cf[3] += 1.0f;   // standalone b_rank (r=15)
                    #pragma unroll
                    for (int pq = 0; pq < 2; pq++) {
                        #pragma unroll
                        for (int e = 0; e < 2; e++) {
                            float P = 0.f;
                            #pragma unroll
                            for (int m = 0; m < 4; m++) {
                                const int nt = 2 * m + pq;
                                P = fmaf(cf[m],
                                         acc[(mt * 8 + nt) * 4 + o * 2 + e] + bias[nt * 2 + e],
                                         P);
                            }
                            mySlab[(pq * 8 + tig * 2 + e) * 132 + s] = P;
                        }
                    }
                }
            }
            __syncthreads();   // slabs complete (also covers GEMM completion)

            // ---- reduce 4 slabs -> carry[a] --------------------------------
            {
                const int q  = tid & 15;
                const int s0 = (tid >> 4) * 8;
                const float* sl = sSlab + q * 132;
                #pragma unroll
                for (int i = 0; i < 8; i++) {
                    const int s = s0 + i;
                    float v = sl[s] + sl[2112 + s] + sl[4224 + s] + sl[6336 + s];
                    sC[s * 64 + a * 16 + q] = v;
                }
            }
            // next iteration's first kc-sync orders reduce-writes vs reads;
            // slab re-writes happen only after that sync as well.
        }
    }
    __syncthreads();

    // ---- epilogue: out = carry @ U_output + b_output -----------------------
    float* sUO = sm;   // 16384 floats in A region
    #pragma unroll
    for (int j = 0; j < 16; j++) {
        const int id = tid + j * 256;
        ((float4*)sUO)[id] = __ldg(((const float4*)UO) + id);
    }
    __syncthreads();
    const int h = tid;
    #pragma unroll
    for (int a = 0; a < 4; a++) {
        float uo[16];
        #pragma unroll
        for (int q = 0; q < 16; q++) uo[q] = sUO[(a * 16 + q) * 256 + h];
        const float bo = __ldg(BO + a * 256 + h);
        #pragma unroll 2
        for (int s = 0; s < 128; s++) {
            const float4* cp4 = (const float4*)(sC + s * 64 + a * 16);
            float4 c0 = cp4[0], c1 = cp4[1], c2 = cp4[2], c3 = cp4[3];
            float v = bo;
            v = fmaf(c0.x, uo[0], v);  v = fmaf(c0.y, uo[1], v);
            v = fmaf(c0.z, uo[2], v);  v = fmaf(c0.w, uo[3], v);
            v = fmaf(c1.x, uo[4], v);  v = fmaf(c1.y, uo[5], v);
            v = fmaf(c1.z, uo[6], v);  v = fmaf(c1.w, uo[7], v);
            v = fmaf(c2.x, uo[8], v);  v = fmaf(c2.y, uo[9], v);
            v = fmaf(c2.z, uo[10], v); v = fmaf(c2.w, uo[11], v);
            v = fmaf(c3.x, uo[12], v); v = fmaf(c3.y, uo[13], v);
            v = fmaf(c3.z, uo[14], v); v = fmaf(c3.w, uo[15], v);
            out[(size_t)(bbase + s) * 1024 + a * 256 + h] = v;
        }
    }
}

// ---- launch ----------------------------------------------------------------
extern "C" void kernel_launch(void* const* d_in, const int* in_sizes, int n_in,
                              void* d_out, int out_size)
{
    const float* NH = (const float*)d_in[0];
    const float* TE = (const float*)d_in[1];
    const float* U  = (const float*)d_in[2];
    const float* Bv = (const float*)d_in[3];
    const float* UT = (const float*)d_in[4];
    const float* BT = (const float*)d_in[5];
    const float* UO = (const float*)d_in[6];
    const float* BO = (const float*)d_in[7];
    float* out = (float*)d_out;

    tt_prep<<<dim3(32, 8), 256>>>(U);

    cudaFuncSetAttribute(tt_main, cudaFuncAttributeMaxDynamicSharedMemorySize,
                         SMEM_BYTES);
    tt_main<<<128, 256, SMEM_BYTES>>>(NH, TE, Bv, UT, BT, UO, BO, out);
}